// round 7
// baseline (speedup 1.0000x reference)
#include <cuda_runtime.h>
#include <cstdint>

// Fixed problem shapes
#define N_   100000
#define R_   4
#define E_   500000
#define IN_  256
#define HID_ 128
#define OUT_ 64
#define M_RN (R_ * N_)
#define SCAN_PB 1024
#define SCAN_NB ((M_RN + SCAN_PB - 1) / SCAN_PB)  // 391
static_assert(SCAN_NB <= 512, "scan_partials single-block capacity");

// Scratch (no allocation allowed -> device globals)
__device__ float g_h[(size_t)R_ * N_ * HID_];  // per-relation transformed features
__device__ float g_out1[(size_t)N_ * HID_];    // layer-1 output (post-ReLU)
__device__ float g_degO[M_RN];                 // rsqrt(max(deg_out,1))
__device__ float g_degI[M_RN];                 // rsqrt(max(deg_in,1))
__device__ int   g_cntO[M_RN];                 // out-degree counts
__device__ int   g_cntI[M_RN];                 // in-degree counts
__device__ int   g_off[M_RN];                  // CSR row offsets (global, exclusive scan)
__device__ int   g_cur[M_RN];                  // fill cursors
__device__ int   g_part[SCAN_NB];              // scan partials
__device__ int   g_csr[R_ * E_];               // src indices bucketed by (r, dst)

// ---------------------------------------------------------------------------
// mma.sync helpers (base-target PTX; works through compute_103 virtual arch)
// ---------------------------------------------------------------------------
__device__ __forceinline__ void mma_tf32(float* c, const uint32_t* a, const uint32_t* b) {
    asm volatile(
        "mma.sync.aligned.m16n8k8.row.col.f32.tf32.tf32.f32 "
        "{%0,%1,%2,%3}, {%4,%5,%6,%7}, {%8,%9}, {%0,%1,%2,%3};"
        : "+f"(c[0]), "+f"(c[1]), "+f"(c[2]), "+f"(c[3])
        : "r"(a[0]), "r"(a[1]), "r"(a[2]), "r"(a[3]), "r"(b[0]), "r"(b[1]));
}

__device__ __forceinline__ float to_tf32(float x) {
    float y;
    asm("cvt.rna.tf32.f32 %0, %1;" : "=f"(y) : "f"(x));
    return y;
}

__device__ __forceinline__ float4 cvt4(float4 v) {
    v.x = to_tf32(v.x); v.y = to_tf32(v.y);
    v.z = to_tf32(v.z); v.w = to_tf32(v.w);
    return v;
}

// ---------------------------------------------------------------------------
// Degree counting + CSR construction
// ---------------------------------------------------------------------------
__global__ void zero_cnt_kernel() {
    int i = blockIdx.x * blockDim.x + threadIdx.x;
    if (i < M_RN) { g_cntO[i] = 0; g_cntI[i] = 0; }
}

__global__ void count_deg_kernel(const int* __restrict__ src, const int* __restrict__ dst) {
    int i = blockIdx.x * blockDim.x + threadIdx.x;
    if (i < R_ * E_) {
        int r = i / E_;
        atomicAdd(&g_cntO[r * N_ + src[i]], 1);
        atomicAdd(&g_cntI[r * N_ + dst[i]], 1);
    }
}

__global__ void finalize_deg_kernel() {
    int i = blockIdx.x * blockDim.x + threadIdx.x;
    if (i < M_RN) {
        g_degO[i] = rsqrtf(fmaxf((float)g_cntO[i], 1.0f));
        g_degI[i] = rsqrtf(fmaxf((float)g_cntI[i], 1.0f));
    }
}

// Pass A: per-block sums of g_cntI (1024 elems / block of 256 threads)
__global__ __launch_bounds__(256) void scan_block_sums() {
    __shared__ int sh[256];
    int tid = threadIdx.x;
    int i0 = blockIdx.x * SCAN_PB + tid * 4;
    int s = 0;
#pragma unroll
    for (int j = 0; j < 4; j++) {
        int i = i0 + j;
        if (i < M_RN) s += g_cntI[i];
    }
    sh[tid] = s;
    __syncthreads();
#pragma unroll
    for (int o = 128; o > 0; o >>= 1) {
        if (tid < o) sh[tid] += sh[tid + o];
        __syncthreads();
    }
    if (tid == 0) g_part[blockIdx.x] = sh[0];
}

// Pass B: single-block exclusive scan of the partials
__global__ __launch_bounds__(512) void scan_partials() {
    __shared__ int sh[512];
    int tid = threadIdx.x;
    sh[tid] = (tid < SCAN_NB) ? g_part[tid] : 0;
    __syncthreads();
#pragma unroll
    for (int o = 1; o < 512; o <<= 1) {
        int v = (tid >= o) ? sh[tid - o] : 0;
        __syncthreads();
        sh[tid] += v;
        __syncthreads();
    }
    if (tid < SCAN_NB) g_part[tid] = tid ? sh[tid - 1] : 0;
}

// Pass C: write global exclusive offsets + fill cursors
__global__ __launch_bounds__(256) void scan_write() {
    __shared__ int sh[256];
    int tid = threadIdx.x;
    int i0 = blockIdx.x * SCAN_PB + tid * 4;
    int v[4], ts = 0;
#pragma unroll
    for (int j = 0; j < 4; j++) {
        int i = i0 + j;
        v[j] = (i < M_RN) ? g_cntI[i] : 0;
        ts += v[j];
    }
    sh[tid] = ts;
    __syncthreads();
#pragma unroll
    for (int o = 1; o < 256; o <<= 1) {
        int t = (tid >= o) ? sh[tid - o] : 0;
        __syncthreads();
        sh[tid] += t;
        __syncthreads();
    }
    int run = g_part[blockIdx.x] + sh[tid] - ts;  // exclusive prefix
#pragma unroll
    for (int j = 0; j < 4; j++) {
        int i = i0 + j;
        if (i < M_RN) { g_off[i] = run; g_cur[i] = run; }
        run += v[j];
    }
}

__global__ void fill_csr_kernel(const int* __restrict__ src, const int* __restrict__ dst) {
    int i = blockIdx.x * blockDim.x + threadIdx.x;
    if (i < R_ * E_) {
        int r = i / E_;
        int pos = atomicAdd(&g_cur[r * N_ + dst[i]], 1);
        g_csr[pos] = src[i];
    }
}

// ---------------------------------------------------------------------------
// TF32 mma.sync GEMM:  C_r = diag(rsqrt_deg_out[r]) * A * W[r]
//   A: [N_, K] fp32 row-major;  W: [R, K, BN] row-major;  C: g_h + r*N_*BN
// BM=128, BK=32, 256 threads (8 warps, 4x2 warp grid). grid = (ceil(N/128), R)
// ---------------------------------------------------------------------------
template <int K, int BN, int LAYER>
__global__ __launch_bounds__(256) void gemm_mma(const float* __restrict__ Ax,
                                                const float* __restrict__ Wall) {
    constexpr int BM = 128, BK = 32;
    constexpr int WN = BN / 2;
    constexpr int NT = WN / 8;
    constexpr int APAD = 4;
    constexpr int BPAD = 8;

    __shared__ float As[BM][BK + APAD];
    __shared__ float Bs[BK][BN + BPAD];

    const int tid = threadIdx.x;
    const int wid = tid >> 5, lane = tid & 31;
    const int g = lane >> 2, t = lane & 3;
    const int wm = wid & 3, wn = wid >> 2;
    const int r = blockIdx.y;
    const int bm = blockIdx.x * BM;

    const float* __restrict__ A = (LAYER == 1) ? Ax : g_out1;  // g_out1 already post-ReLU
    const float* __restrict__ W = Wall + (size_t)r * K * BN;
    float* __restrict__ C = g_h + (size_t)r * N_ * BN;

    float acc[2][NT][4];
#pragma unroll
    for (int m2 = 0; m2 < 2; m2++)
#pragma unroll
        for (int nt = 0; nt < NT; nt++)
#pragma unroll
            for (int i = 0; i < 4; i++) acc[m2][nt][i] = 0.0f;

    for (int kt = 0; kt < K / BK; kt++) {
#pragma unroll
        for (int l = 0; l < 4; l++) {
            int idx = tid + l * 256;
            int row = idx >> 3, q = idx & 7;
            int grow = bm + row;
            float4 v = make_float4(0.f, 0.f, 0.f, 0.f);
            if (grow < N_) v = *(const float4*)(A + (size_t)grow * K + kt * BK + q * 4);
            *(float4*)&As[row][q * 4] = cvt4(v);
        }
#pragma unroll
        for (int l = 0; l < (BK * BN / 4) / 256; l++) {
            int idx = tid + l * 256;
            int krow = idx / (BN / 4), c4 = idx % (BN / 4);
            float4 v = *(const float4*)(W + (size_t)(kt * BK + krow) * BN + c4 * 4);
            *(float4*)&Bs[krow][c4 * 4] = cvt4(v);
        }
        __syncthreads();

#pragma unroll
        for (int ks = 0; ks < BK / 8; ks++) {
            const int kb = ks * 8;
            uint32_t a[2][4];
#pragma unroll
            for (int m2 = 0; m2 < 2; m2++) {
                int row = wm * 32 + m2 * 16;
                a[m2][0] = __float_as_uint(As[row + g][kb + t]);
                a[m2][1] = __float_as_uint(As[row + 8 + g][kb + t]);
                a[m2][2] = __float_as_uint(As[row + g][kb + t + 4]);
                a[m2][3] = __float_as_uint(As[row + 8 + g][kb + t + 4]);
            }
#pragma unroll
            for (int nt = 0; nt < NT; nt++) {
                uint32_t b[2];
                int col = wn * WN + nt * 8 + g;
                b[0] = __float_as_uint(Bs[kb + t][col]);
                b[1] = __float_as_uint(Bs[kb + t + 4][col]);
                mma_tf32(acc[0][nt], a[0], b);
                mma_tf32(acc[1][nt], a[1], b);
            }
        }
        __syncthreads();
    }

#pragma unroll
    for (int m2 = 0; m2 < 2; m2++) {
        int row0 = bm + wm * 32 + m2 * 16 + g;
        int row1 = row0 + 8;
        float s0 = (row0 < N_) ? g_degO[r * N_ + row0] : 0.f;
        float s1 = (row1 < N_) ? g_degO[r * N_ + row1] : 0.f;
#pragma unroll
        for (int nt = 0; nt < NT; nt++) {
            int col = wn * WN + nt * 8 + t * 2;
            if (row0 < N_) {
                float2 v = make_float2(acc[m2][nt][0] * s0, acc[m2][nt][1] * s0);
                *(float2*)(C + (size_t)row0 * BN + col) = v;
            }
            if (row1 < N_) {
                float2 v = make_float2(acc[m2][nt][2] * s1, acc[m2][nt][3] * s1);
                *(float2*)(C + (size_t)row1 * BN + col) = v;
            }
        }
    }
}

// ---------------------------------------------------------------------------
// CSR gather, layer 1 (F=128): one warp per dst node, lane owns 4 floats.
//   out1[n] = relu( sum_r ( degI_r[n] * sum_{e in CSR(r,n)} h_r[src_e] + b1[r] ) )
// ---------------------------------------------------------------------------
__global__ __launch_bounds__(256) void gather1_kernel(const float* __restrict__ b1) {
    int warp = (blockIdx.x * 256 + threadIdx.x) >> 5;
    int lane = threadIdx.x & 31;
    if (warp >= N_) return;
    const int n = warp;

    float4 acc = make_float4(0.f, 0.f, 0.f, 0.f);
#pragma unroll
    for (int r = 0; r < R_; r++) {
        float4 b = *(const float4*)(b1 + r * HID_ + lane * 4);
        acc.x += b.x; acc.y += b.y; acc.z += b.z; acc.w += b.w;
    }

#pragma unroll
    for (int r = 0; r < R_; r++) {
        const int idx = r * N_ + n;
        const int off = g_off[idx];
        const int cnt = g_cntI[idx];
        const float sc = g_degI[idx];
        const float* __restrict__ hb = g_h + (size_t)r * N_ * HID_;
        float4 part = make_float4(0.f, 0.f, 0.f, 0.f);
        for (int base = 0; base < cnt; base += 32) {
            int e = base + lane;
            int si = (e < cnt) ? g_csr[off + e] : 0;
            const int m = min(32, cnt - base);
#pragma unroll 4
            for (int j = 0; j < m; j++) {
                int s = __shfl_sync(0xffffffffu, si, j);
                float4 hv = *(const float4*)(hb + (size_t)s * HID_ + lane * 4);
                part.x += hv.x; part.y += hv.y; part.z += hv.z; part.w += hv.w;
            }
        }
        acc.x += sc * part.x; acc.y += sc * part.y;
        acc.z += sc * part.z; acc.w += sc * part.w;
    }

    // ReLU folded here (g_out1's only consumer wants relu(out1))
    float4 o = make_float4(fmaxf(acc.x, 0.f), fmaxf(acc.y, 0.f),
                           fmaxf(acc.z, 0.f), fmaxf(acc.w, 0.f));
    *(float4*)(g_out1 + (size_t)n * HID_ + lane * 4) = o;
}

// ---------------------------------------------------------------------------
// CSR gather, layer 2 (F=64): one warp per dst node, lane owns 2 floats.
// ---------------------------------------------------------------------------
__global__ __launch_bounds__(256) void gather2_kernel(const float* __restrict__ b2,
                                                      float* __restrict__ out) {
    int warp = (blockIdx.x * 256 + threadIdx.x) >> 5;
    int lane = threadIdx.x & 31;
    if (warp >= N_) return;
    const int n = warp;

    float2 acc = make_float2(0.f, 0.f);
#pragma unroll
    for (int r = 0; r < R_; r++) {
        float2 b = *(const float2*)(b2 + r * OUT_ + lane * 2);
        acc.x += b.x; acc.y += b.y;
    }

#pragma unroll
    for (int r = 0; r < R_; r++) {
        const int idx = r * N_ + n;
        const int off = g_off[idx];
        const int cnt = g_cntI[idx];
        const float sc = g_degI[idx];
        const float* __restrict__ hb = g_h + (size_t)r * N_ * OUT_;
        float2 part = make_float2(0.f, 0.f);
        for (int base = 0; base < cnt; base += 32) {
            int e = base + lane;
            int si = (e < cnt) ? g_csr[off + e] : 0;
            const int m = min(32, cnt - base);
#pragma unroll 4
            for (int j = 0; j < m; j++) {
                int s = __shfl_sync(0xffffffffu, si, j);
                float2 hv = *(const float2*)(hb + (size_t)s * OUT_ + lane * 2);
                part.x += hv.x; part.y += hv.y;
            }
        }
        acc.x += sc * part.x; acc.y += sc * part.y;
    }

    *(float2*)(out + (size_t)n * OUT_ + lane * 2) = acc;
}

// ---------------------------------------------------------------------------
// Launch
// ---------------------------------------------------------------------------
extern "C" void kernel_launch(void* const* d_in, const int* in_sizes, int n_in,
                              void* d_out, int out_size) {
    const float* x    = (const float*)d_in[0];
    const int*   esrc = (const int*)d_in[1];
    const int*   edst = (const int*)d_in[2];
    const float* W1   = (const float*)d_in[3];
    const float* b1   = (const float*)d_in[4];
    const float* W2   = (const float*)d_in[5];
    const float* b2   = (const float*)d_in[6];
    float* out = (float*)d_out;

    const int mblocks = (N_ + 127) / 128;
    const int gblocks = (N_ * 32 + 255) / 256;  // one warp per node

    // Degrees + CSR (shared by both layers)
    zero_cnt_kernel<<<(M_RN + 255) / 256, 256>>>();
    count_deg_kernel<<<(R_ * E_ + 255) / 256, 256>>>(esrc, edst);
    scan_block_sums<<<SCAN_NB, 256>>>();
    scan_partials<<<1, 512>>>();
    scan_write<<<SCAN_NB, 256>>>();
    fill_csr_kernel<<<(R_ * E_ + 255) / 256, 256>>>(esrc, edst);
    finalize_deg_kernel<<<(M_RN + 255) / 256, 256>>>();

    // Layer 1
    gemm_mma<IN_, HID_, 1><<<dim3(mblocks, R_), 256>>>(x, W1);
    gather1_kernel<<<gblocks, 256>>>(b1);

    // Layer 2 (ReLU already applied by gather1)
    gemm_mma<HID_, OUT_, 2><<<dim3(mblocks, R_), 256>>>(x, W2);
    gather2_kernel<<<gblocks, 256>>>(b2, out);
}

// round 11
// speedup vs baseline: 1.0754x; 1.0754x over previous
#include <cuda_runtime.h>
#include <cstdint>

// Fixed problem shapes
#define N_   100000
#define R_   4
#define E_   500000
#define IN_  256
#define HID_ 128
#define OUT_ 64
#define M_RN (R_ * N_)

// Scratch (no allocation allowed -> device globals)
__device__ float g_h[(size_t)R_ * N_ * HID_];  // per-relation transformed features
__device__ float g_out1[(size_t)N_ * HID_];    // layer-1 accumulated output (pre-ReLU)
__device__ float g_degO[M_RN];                 // rsqrt(max(deg_out,1))
__device__ float g_degI[M_RN];                 // rsqrt(max(deg_in,1))

// ---------------------------------------------------------------------------
// mma.sync helpers (base-target PTX; works through compute_103 virtual arch)
// ---------------------------------------------------------------------------
__device__ __forceinline__ void mma_tf32(float* c, const uint32_t* a, const uint32_t* b) {
    asm volatile(
        "mma.sync.aligned.m16n8k8.row.col.f32.tf32.tf32.f32 "
        "{%0,%1,%2,%3}, {%4,%5,%6,%7}, {%8,%9}, {%0,%1,%2,%3};"
        : "+f"(c[0]), "+f"(c[1]), "+f"(c[2]), "+f"(c[3])
        : "r"(a[0]), "r"(a[1]), "r"(a[2]), "r"(a[3]), "r"(b[0]), "r"(b[1]));
}

__device__ __forceinline__ float to_tf32(float x) {
    float y;
    asm("cvt.rna.tf32.f32 %0, %1;" : "=f"(y) : "f"(x));
    return y;
}

__device__ __forceinline__ float4 cvt4(float4 v) {
    v.x = to_tf32(v.x); v.y = to_tf32(v.y);
    v.z = to_tf32(v.z); v.w = to_tf32(v.w);
    return v;
}

// ---------------------------------------------------------------------------
// Degree kernels
// ---------------------------------------------------------------------------
__global__ void zero_deg_kernel() {
    int i = blockIdx.x * blockDim.x + threadIdx.x;
    if (i < M_RN) { g_degO[i] = 0.0f; g_degI[i] = 0.0f; }
}

__global__ void count_deg_kernel(const int* __restrict__ src, const int* __restrict__ dst) {
    int i = blockIdx.x * blockDim.x + threadIdx.x;
    if (i < R_ * E_) {
        int r = i / E_;
        atomicAdd(&g_degO[r * N_ + src[i]], 1.0f);
        atomicAdd(&g_degI[r * N_ + dst[i]], 1.0f);
    }
}

__global__ void finalize_deg_kernel() {
    int i = blockIdx.x * blockDim.x + threadIdx.x;
    if (i < M_RN) {
        g_degO[i] = rsqrtf(fmaxf(g_degO[i], 1.0f));
        g_degI[i] = rsqrtf(fmaxf(g_degI[i], 1.0f));
    }
}

// ---------------------------------------------------------------------------
// Output init (float4 vectorized): out[n][k] = sum_r b[r][k]
// ---------------------------------------------------------------------------
__global__ void init_out1_kernel(const float* __restrict__ b1) {
    int i = blockIdx.x * blockDim.x + threadIdx.x;   // one float4 per thread
    if (i < N_ * (HID_ / 4)) {
        int c4 = i & (HID_ / 4 - 1);
        float4 s = make_float4(0.f, 0.f, 0.f, 0.f);
#pragma unroll
        for (int r = 0; r < R_; r++) {
            float4 b = *(const float4*)(b1 + r * HID_ + c4 * 4);
            s.x += b.x; s.y += b.y; s.z += b.z; s.w += b.w;
        }
        *(float4*)(g_out1 + (size_t)i * 4) = s;
    }
}

__global__ void init_out2_kernel(const float* __restrict__ b2, float* __restrict__ out) {
    int i = blockIdx.x * blockDim.x + threadIdx.x;
    if (i < N_ * (OUT_ / 4)) {
        int c4 = i & (OUT_ / 4 - 1);
        float4 s = make_float4(0.f, 0.f, 0.f, 0.f);
#pragma unroll
        for (int r = 0; r < R_; r++) {
            float4 b = *(const float4*)(b2 + r * OUT_ + c4 * 4);
            s.x += b.x; s.y += b.y; s.z += b.z; s.w += b.w;
        }
        *(float4*)(out + (size_t)i * 4) = s;
    }
}

// ---------------------------------------------------------------------------
// TF32 mma.sync GEMM:  C_r = diag(rsqrt_deg_out[r]) * relu?(A) * W[r]
//   A: [N_, K] fp32 row-major;  W: [R, K, BN] row-major;  C: g_h + r*N_*BN
// BM=128, BK=32, 256 threads. 8 warps as 2(M) x 4(N): warp tile 64 x BN/4.
// grid = (ceil(N/128), R)
// ---------------------------------------------------------------------------
template <int K, int BN, int LAYER>
__global__ __launch_bounds__(256) void gemm_mma(const float* __restrict__ Ax,
                                                const float* __restrict__ Wall) {
    constexpr int BM = 128, BK = 32;
    constexpr int WN = BN / 4;   // warp n-tile: 32 (L1) / 16 (L2)
    constexpr int NT = WN / 8;   // 4 / 2
    constexpr int APAD = 4;      // stride 36: bank = 4g+t -> conflict-free frags
    constexpr int BPAD = 8;      // stride BN+8 (≡8 mod 32): bank = 8t+g -> conflict-free

    __shared__ float As[BM][BK + APAD];
    __shared__ float Bs[BK][BN + BPAD];

    const int tid = threadIdx.x;
    const int wid = tid >> 5, lane = tid & 31;
    const int g = lane >> 2, t = lane & 3;
    const int wm = wid & 1, wn = wid >> 1;   // 2 x 4 warp grid
    const int r = blockIdx.y;
    const int bm = blockIdx.x * BM;

    const float* __restrict__ A = (LAYER == 1) ? Ax : g_out1;
    const float* __restrict__ W = Wall + (size_t)r * K * BN;
    float* __restrict__ C = g_h + (size_t)r * N_ * BN;

    float acc[4][NT][4];
#pragma unroll
    for (int m2 = 0; m2 < 4; m2++)
#pragma unroll
        for (int nt = 0; nt < NT; nt++)
#pragma unroll
            for (int i = 0; i < 4; i++) acc[m2][nt][i] = 0.0f;

    for (int kt = 0; kt < K / BK; kt++) {
        // A tile: 128 x 32 fp32 = 1024 float4 over 256 threads
#pragma unroll
        for (int l = 0; l < 4; l++) {
            int idx = tid + l * 256;
            int row = idx >> 3, q = idx & 7;
            int grow = bm + row;
            float4 v = make_float4(0.f, 0.f, 0.f, 0.f);
            if (grow < N_) {
                v = *(const float4*)(A + (size_t)grow * K + kt * BK + q * 4);
                if (LAYER == 2) {
                    v.x = fmaxf(v.x, 0.f); v.y = fmaxf(v.y, 0.f);
                    v.z = fmaxf(v.z, 0.f); v.w = fmaxf(v.w, 0.f);
                }
            }
            *(float4*)&As[row][q * 4] = cvt4(v);
        }
        // B tile: 32 x BN fp32
#pragma unroll
        for (int l = 0; l < (BK * BN / 4) / 256; l++) {
            int idx = tid + l * 256;
            int krow = idx / (BN / 4), c4 = idx % (BN / 4);
            float4 v = *(const float4*)(W + (size_t)(kt * BK + krow) * BN + c4 * 4);
            *(float4*)&Bs[krow][c4 * 4] = cvt4(v);
        }
        __syncthreads();

#pragma unroll
        for (int ks = 0; ks < BK / 8; ks++) {
            const int kb = ks * 8;
            uint32_t a[4][4];
#pragma unroll
            for (int m2 = 0; m2 < 4; m2++) {
                int row = wm * 64 + m2 * 16;
                a[m2][0] = __float_as_uint(As[row + g][kb + t]);
                a[m2][1] = __float_as_uint(As[row + 8 + g][kb + t]);
                a[m2][2] = __float_as_uint(As[row + g][kb + t + 4]);
                a[m2][3] = __float_as_uint(As[row + 8 + g][kb + t + 4]);
            }
#pragma unroll
            for (int nt = 0; nt < NT; nt++) {
                uint32_t b[2];
                int col = wn * WN + nt * 8 + g;
                b[0] = __float_as_uint(Bs[kb + t][col]);
                b[1] = __float_as_uint(Bs[kb + t + 4][col]);
#pragma unroll
                for (int m2 = 0; m2 < 4; m2++) mma_tf32(acc[m2][nt], a[m2], b);
            }
        }
        __syncthreads();
    }

    // Epilogue: scale rows by rsqrt(deg_out) (commutes with GEMM), store fp32
#pragma unroll
    for (int m2 = 0; m2 < 4; m2++) {
        int row0 = bm + wm * 64 + m2 * 16 + g;
        int row1 = row0 + 8;
        float s0 = (row0 < N_) ? g_degO[r * N_ + row0] : 0.f;
        float s1 = (row1 < N_) ? g_degO[r * N_ + row1] : 0.f;
#pragma unroll
        for (int nt = 0; nt < NT; nt++) {
            int col = wn * WN + nt * 8 + t * 2;
            if (row0 < N_) {
                float2 v = make_float2(acc[m2][nt][0] * s0, acc[m2][nt][1] * s0);
                *(float2*)(C + (size_t)row0 * BN + col) = v;
            }
            if (row1 < N_) {
                float2 v = make_float2(acc[m2][nt][2] * s1, acc[m2][nt][3] * s1);
                *(float2*)(C + (size_t)row1 * BN + col) = v;
            }
        }
    }
}

// ---------------------------------------------------------------------------
// Edge scatter (all relations, grid.y = r): out[dst] += rsqrt(deg_in)[dst]*h_r[src]
// One thread per (edge, float4-chunk); red.global.add.v4 (no return).
// ---------------------------------------------------------------------------
template <int F, int LAYER>
__global__ __launch_bounds__(256) void scatter_all_kernel(const int* __restrict__ esrc,
                                                          const int* __restrict__ edst,
                                                          float* __restrict__ outp) {
    constexpr int P = F / 4;
    const int r = blockIdx.y;
    int idx = blockIdx.x * blockDim.x + threadIdx.x;
    if (idx >= E_ * P) return;
    int e = idx / P;
    int p = idx % P;
    int s = esrc[r * E_ + e];
    int d = edst[r * E_ + e];
    float sc = g_degI[r * N_ + d];
    float4 v = *(const float4*)(g_h + (size_t)r * N_ * F + (size_t)s * F + p * 4);
    float* o = ((LAYER == 1) ? g_out1 : outp) + (size_t)d * F + p * 4;
    asm volatile("red.global.add.v4.f32 [%0], {%1, %2, %3, %4};"
                 :: "l"(o), "f"(v.x * sc), "f"(v.y * sc), "f"(v.z * sc), "f"(v.w * sc)
                 : "memory");
}

// ---------------------------------------------------------------------------
// Launch (gemm_mma L1 is the 4th launch -> lands in the fixed ncu window)
// ---------------------------------------------------------------------------
extern "C" void kernel_launch(void* const* d_in, const int* in_sizes, int n_in,
                              void* d_out, int out_size) {
    const float* x    = (const float*)d_in[0];
    const int*   esrc = (const int*)d_in[1];
    const int*   edst = (const int*)d_in[2];
    const float* W1   = (const float*)d_in[3];
    const float* b1   = (const float*)d_in[4];
    const float* W2   = (const float*)d_in[5];
    const float* b2   = (const float*)d_in[6];
    float* out = (float*)d_out;

    const int mblocks = (N_ + 127) / 128;

    // Degrees (shared by both layers)
    zero_deg_kernel<<<(M_RN + 255) / 256, 256>>>();                     // 1
    count_deg_kernel<<<(R_ * E_ + 255) / 256, 256>>>(esrc, edst);       // 2
    finalize_deg_kernel<<<(M_RN + 255) / 256, 256>>>();                 // 3

    // Layer 1
    gemm_mma<IN_, HID_, 1><<<dim3(mblocks, R_), 256>>>(x, W1);          // 4 (profiled)
    init_out1_kernel<<<(N_ * (HID_ / 4) + 255) / 256, 256>>>(b1);       // 5
    scatter_all_kernel<HID_, 1>
        <<<dim3((E_ * (HID_ / 4) + 255) / 256, R_), 256>>>(esrc, edst, nullptr);

    // Layer 2 (ReLU folded into GEMM A-load)
    gemm_mma<HID_, OUT_, 2><<<dim3(mblocks, R_), 256>>>(x, W2);
    init_out2_kernel<<<(N_ * (OUT_ / 4) + 255) / 256, 256>>>(b2, out);
    scatter_all_kernel<OUT_, 2>
        <<<dim3((E_ * (OUT_ / 4) + 255) / 256, R_), 256>>>(esrc, edst, out);
}